// round 15
// baseline (speedup 1.0000x reference)
#include <cuda_runtime.h>
#include <cuda_fp16.h>
#include <cstdint>

#define N_NODES 50000
#define E_MAX   600000
#define D_DIM   128
#define R_REL   4
#define L_LAY   3
#define KTOT    640           // 128 (root) + 4*128 (W)
#define KC      64            // K per pipeline stage
#define NCHUNK  (KTOT / KC)   // 10
#define NR4     (N_NODES * R_REL)

// ---------------------------------------------------------------------------
// Static device scratch (no runtime allocation allowed)
// ---------------------------------------------------------------------------
__device__ __half g_xA[(size_t)N_NODES * D_DIM];
__device__ __half g_xB[(size_t)N_NODES * D_DIM];
__device__ __half g_h [(size_t)N_NODES * R_REL * D_DIM];
// Transposed fp16 stacked weights: Wt[l][n][k], k in [0,640)
__device__ __half g_Wt[L_LAY][D_DIM][KTOT];
// Edge sort (key = dst*4 + relation)
__device__ int g_sorted[E_MAX];
__device__ int g_rowstart[NR4 + 1];
__device__ int g_cursor[NR4];
__device__ int g_bsum[256];

// ---------------------------------------------------------------------------
// Helpers
// ---------------------------------------------------------------------------
#define SWZ128(off) ((off) ^ (((off) >> 3) & 0x70))

__device__ __forceinline__ uint32_t smem_u32(const void* p) {
    uint32_t a;
    asm("{ .reg .u64 t; cvta.to.shared.u64 t, %1; cvt.u32.u64 %0, t; }"
        : "=r"(a) : "l"(p));
    return a;
}
__device__ __forceinline__ void cp16(uint32_t d, const void* s) {
    asm volatile("cp.async.cg.shared.global [%0], [%1], 16;" :: "r"(d), "l"(s));
}
__device__ __forceinline__ void cp16z(uint32_t d, const void* s, int bytes) {
    asm volatile("cp.async.cg.shared.global [%0], [%1], 16, %2;"
                 :: "r"(d), "l"(s), "r"(bytes));
}
#define CP_COMMIT() asm volatile("cp.async.commit_group;" ::: "memory")
#define CP_WAIT(N)  asm volatile("cp.async.wait_group %0;" :: "n"(N) : "memory")

__device__ __forceinline__ void ldmatrix_x4(uint32_t& r0, uint32_t& r1,
                                            uint32_t& r2, uint32_t& r3,
                                            uint32_t addr) {
    asm volatile("ldmatrix.sync.aligned.m8n8.x4.shared.b16 {%0,%1,%2,%3}, [%4];"
                 : "=r"(r0), "=r"(r1), "=r"(r2), "=r"(r3) : "r"(addr));
}
__device__ __forceinline__ void mma_f16(float* c, const uint32_t* a,
                                        uint32_t b0, uint32_t b1) {
    asm volatile(
        "mma.sync.aligned.m16n8k16.row.col.f32.f16.f16.f32 "
        "{%0,%1,%2,%3}, {%4,%5,%6,%7}, {%8,%9}, {%0,%1,%2,%3};"
        : "+f"(c[0]), "+f"(c[1]), "+f"(c[2]), "+f"(c[3])
        : "r"(a[0]), "r"(a[1]), "r"(a[2]), "r"(a[3]), "r"(b0), "r"(b1));
}

__device__ __forceinline__ uint32_t pack2h(float a, float b) {
    __half2 h = __floats2half2_rn(a, b);
    return *reinterpret_cast<uint32_t*>(&h);
}

// ---------------------------------------------------------------------------
// Kernel: embed -> fp16, weight prep, AND cursor zeroing (disjoint ranges)
// ---------------------------------------------------------------------------
__global__ void embedprep_kernel(const int* __restrict__ node_type,
                                 const float* __restrict__ emb,
                                 __half* __restrict__ x,
                                 const float* __restrict__ W,
                                 const float* __restrict__ root,
                                 int n, int n4)
{
    const int nEmb = n * 32;
    const int TOT  = L_LAY * D_DIM * KTOT;
    int idx = blockIdx.x * blockDim.x + threadIdx.x;
    if (idx < nEmb) {
        int node = idx >> 5;
        int q    = idx & 31;
        float4 v = reinterpret_cast<const float4*>(emb + (size_t)node_type[node] * D_DIM)[q];
        *reinterpret_cast<uint2*>(x + (size_t)node * D_DIM + q * 4) =
            make_uint2(pack2h(v.x, v.y), pack2h(v.z, v.w));
        return;
    }
    idx -= nEmb;
    if (idx < TOT) {
        int l  = idx / (D_DIM * KTOT);
        int r0 = idx % (D_DIM * KTOT);
        int nn = r0 / KTOT;
        int k  = r0 % KTOT;
        float v;
        if (k < D_DIM) {
            v = root[((size_t)l * D_DIM + k) * D_DIM + nn];
        } else {
            int kk = k - D_DIM;
            int r  = kk >> 7;
            int k2 = kk & 127;
            v = W[((((size_t)l * R_REL) + r) * D_DIM + k2) * D_DIM + nn];
        }
        g_Wt[l][nn][k] = __float2half_rn(v);
        return;
    }
    idx -= TOT;
    if (idx < n4) g_cursor[idx] = 0;
}

// ---------------------------------------------------------------------------
// Counting sort of edges by key = dst*4 + rel
// ---------------------------------------------------------------------------
__global__ void hist_kernel(const int* __restrict__ edge_index,
                            const int* __restrict__ edge_type, int E)
{
    int idx = blockIdx.x * blockDim.x + threadIdx.x;
    if (idx >= E) return;
    atomicAdd(&g_cursor[edge_index[E + idx] * 4 + edge_type[idx]], 1);
}

__global__ __launch_bounds__(1024)
void scanA_kernel(int n4)
{
    __shared__ int warp_sums[32];
    const int tid  = threadIdx.x;
    const int lane = tid & 31;
    const int wrp  = tid >> 5;
    const int i    = blockIdx.x * 1024 + tid;
    int v = (i < n4) ? g_cursor[i] : 0;
    int x = v;
    #pragma unroll
    for (int d = 1; d < 32; d <<= 1) {
        int t = __shfl_up_sync(0xffffffffu, x, d);
        if (lane >= d) x += t;
    }
    if (lane == 31) warp_sums[wrp] = x;
    __syncthreads();
    if (wrp == 0) {
        int s = warp_sums[lane];
        #pragma unroll
        for (int d = 1; d < 32; d <<= 1) {
            int t = __shfl_up_sync(0xffffffffu, s, d);
            if (lane >= d) s += t;
        }
        warp_sums[lane] = s;
    }
    __syncthreads();
    int excl = x - v + (wrp ? warp_sums[wrp - 1] : 0);
    if (i < n4) g_rowstart[i] = excl;
    if (tid == 1023) g_bsum[blockIdx.x] = excl + v;   // raw block total
}

__global__ __launch_bounds__(1024)
void scanC_kernel(int n4, int E)
{
    __shared__ int s_off;
    const int tid = threadIdx.x;
    if (tid == 0) s_off = 0;
    __syncthreads();
    int p = 0;
    for (int i = tid; i < blockIdx.x; i += blockDim.x) p += g_bsum[i];
    if (p) atomicAdd(&s_off, p);
    __syncthreads();
    const int off = s_off;
    const int i = blockIdx.x * 1024 + tid;
    if (i < n4) {
        int v = g_rowstart[i] + off;
        g_rowstart[i] = v;
        g_cursor[i]   = v;
    } else if (i == n4) {
        g_rowstart[n4] = E;
    }
}

__global__ void reorder_kernel(const int* __restrict__ edge_index,
                               const int* __restrict__ edge_type, int E)
{
    int idx = blockIdx.x * blockDim.x + threadIdx.x;
    if (idx >= E) return;
    int key = edge_index[E + idx] * 4 + edge_type[idx];
    int pos = atomicAdd(&g_cursor[key], 1);
    g_sorted[pos] = edge_index[idx];   // src only
}

// ---------------------------------------------------------------------------
// Kernel: CSR aggregation. ONE WARP PER (dst, relation) SEGMENT — 4x more
// parallelism than per-dst; short independent loops, fixed-register acc.
// w in [0, n4): dst = w>>2, r = w&3; h row offset = w * D_DIM.
// ---------------------------------------------------------------------------
__global__ __launch_bounds__(256)
void agg_kernel(const __half* __restrict__ x,
                __half* __restrict__ h, int n4)
{
    int w = (blockIdx.x * blockDim.x + threadIdx.x) >> 5;
    int lane = threadIdx.x & 31;
    if (w >= n4) return;

    const int e0 = g_rowstart[w];
    const int e1 = g_rowstart[w + 1];
    float a0 = 0.f, a1 = 0.f, a2 = 0.f, a3 = 0.f;
    #pragma unroll 4
    for (int e = e0; e < e1; e++) {
        int src = __ldg(&g_sorted[e]);
        uint2 v = *reinterpret_cast<const uint2*>(
            x + (size_t)src * D_DIM + lane * 4);
        float2 f0 = __half22float2(*reinterpret_cast<__half2*>(&v.x));
        float2 f1 = __half22float2(*reinterpret_cast<__half2*>(&v.y));
        a0 += f0.x; a1 += f0.y; a2 += f1.x; a3 += f1.y;
    }
    size_t o = (size_t)w * D_DIM + lane * 4;
    *reinterpret_cast<uint2*>(h + o) =
        make_uint2(pack2h(a0, a1), pack2h(a2, a3));
}

// ---------------------------------------------------------------------------
// GEMM: y[m,0:128] = lrelu( [x|h][m,0:640] @ Wt^T + bias )   (unchanged)
// ---------------------------------------------------------------------------
#define ST_A   0
#define ST_B   16384
#define ST_SIZE 32768
#define SM_TOTAL (2 * ST_SIZE)

__global__ __launch_bounds__(256, 2)
void gemm_mma_kernel(const __half* __restrict__ x,
                     const __half* __restrict__ h,
                     const __half* __restrict__ Wt,    // [128][640]
                     const float* __restrict__ bias_l,
                     __half* __restrict__ yh,          // null on final
                     float* __restrict__ yf32,         // null unless final
                     int n)
{
    extern __shared__ __align__(1024) char smem[];
    const uint32_t sb = smem_u32(smem);
    const int tid    = threadIdx.x;
    const int lane   = tid & 31;
    const int wid    = tid >> 5;
    const int warp_m = wid >> 2;
    const int warp_n = wid & 3;
    const int m0     = blockIdx.x * 128;

    float acc[4][4][4];
    #pragma unroll
    for (int i = 0; i < 4; i++)
        #pragma unroll
        for (int j = 0; j < 4; j++)
            #pragma unroll
            for (int q = 0; q < 4; q++) acc[i][j][q] = 0.f;

    auto load_stage = [&](int stage, int c) {
        const __half* A;
        int lda;
        if (c < 2) { A = x + c * KC; lda = D_DIM; }
        else       { A = h + (c - 2) * KC; lda = R_REL * D_DIM; }
        const uint32_t base = sb + stage * ST_SIZE;
        #pragma unroll
        for (int it = 0; it < 4; it++) {
            int f   = it * 256 + tid;
            int row = f >> 3;
            int q   = f & 7;
            uint32_t off = SWZ128((uint32_t)(row * 128 + q * 16));
            int bytes = (m0 + row < n) ? 16 : 0;
            cp16z(base + ST_A + off, A + (size_t)(m0 + row) * lda + q * 8, bytes);
        }
        #pragma unroll
        for (int it = 0; it < 4; it++) {
            int f   = it * 256 + tid;
            int row = f >> 3;
            int q   = f & 7;
            uint32_t off = SWZ128((uint32_t)(row * 128 + q * 16));
            cp16(base + ST_B + off, Wt + (size_t)row * KTOT + c * KC + q * 8);
        }
    };

    load_stage(0, 0);
    CP_COMMIT();

    for (int c = 0; c < NCHUNK; c++) {
        if (c + 1 < NCHUNK) {
            load_stage((c + 1) & 1, c + 1);
            CP_COMMIT();
            CP_WAIT(1);
        } else {
            CP_WAIT(0);
        }
        __syncthreads();

        const uint32_t base = sb + (c & 1) * ST_SIZE;
        #pragma unroll
        for (int ks = 0; ks < 4; ks++) {
            const int k0 = ks * 16;
            uint32_t b[2][4];
            #pragma unroll
            for (int p = 0; p < 2; p++) {
                int nb   = warp_n * 32 + p * 16;
                int row  = nb + (lane & 7) + ((lane >> 4) << 3);
                uint32_t off = SWZ128((uint32_t)(row * 128 + k0 * 2 + ((lane & 8) ? 16 : 0)));
                ldmatrix_x4(b[p][0], b[p][1], b[p][2], b[p][3], base + ST_B + off);
            }
            #pragma unroll
            for (int m = 0; m < 4; m++) {
                int row  = warp_m * 64 + m * 16 + (lane & 15);
                uint32_t off = SWZ128((uint32_t)(row * 128 + k0 * 2 + ((lane >> 4) << 4)));
                uint32_t a[4];
                ldmatrix_x4(a[0], a[1], a[2], a[3], base + ST_A + off);
                #pragma unroll
                for (int p = 0; p < 2; p++) {
                    #pragma unroll
                    for (int t = 0; t < 2; t++) {
                        int nt = p * 2 + t;
                        mma_f16(acc[m][nt], a, b[p][t * 2], b[p][t * 2 + 1]);
                    }
                }
            }
        }
        __syncthreads();
    }

    // ---- epilogue: bias + leaky_relu ----
    #pragma unroll
    for (int nt = 0; nt < 4; nt++) {
        int col = warp_n * 32 + nt * 8 + (lane & 3) * 2;
        float2 b = *reinterpret_cast<const float2*>(bias_l + col);
        #pragma unroll
        for (int m = 0; m < 4; m++) {
            int row0 = m0 + warp_m * 64 + m * 16 + (lane >> 2);
            #pragma unroll
            for (int half = 0; half < 2; half++) {
                int row = row0 + half * 8;
                if (row < n) {
                    float v0 = acc[m][nt][half * 2 + 0] + b.x;
                    float v1 = acc[m][nt][half * 2 + 1] + b.y;
                    v0 = v0 > 0.f ? v0 : 0.01f * v0;
                    v1 = v1 > 0.f ? v1 : 0.01f * v1;
                    if (yf32) {
                        *reinterpret_cast<float2*>(yf32 + (size_t)row * D_DIM + col) =
                            make_float2(v0, v1);
                    } else {
                        *reinterpret_cast<uint32_t*>(yh + (size_t)row * D_DIM + col) =
                            pack2h(v0, v1);
                    }
                }
            }
        }
    }
}

// ---------------------------------------------------------------------------
// Launch
// ---------------------------------------------------------------------------
extern "C" void kernel_launch(void* const* d_in, const int* in_sizes, int n_in,
                              void* d_out, int out_size)
{
    const int*   node_type  = (const int*)  d_in[0];
    const int*   edge_index = (const int*)  d_in[1];
    const int*   edge_type  = (const int*)  d_in[2];
    const float* emb        = (const float*)d_in[3];
    const float* W          = (const float*)d_in[4];   // [L,R,D,D]
    const float* root       = (const float*)d_in[5];   // [L,D,D]
    const float* bias       = (const float*)d_in[6];   // [L,D]
    float*       out        = (float*)d_out;

    const int n  = in_sizes[0];
    const int E  = in_sizes[2];
    const int n4 = n * R_REL;

    __half *xA, *xB, *h, *wt;
    cudaGetSymbolAddress((void**)&xA,  g_xA);
    cudaGetSymbolAddress((void**)&xB,  g_xB);
    cudaGetSymbolAddress((void**)&h,   g_h);
    cudaGetSymbolAddress((void**)&wt,  g_Wt);

    cudaFuncSetAttribute(gemm_mma_kernel,
                         cudaFuncAttributeMaxDynamicSharedMemorySize, SM_TOTAL);

    // --- one-time per launch: embed+prep+cursor-zero, edge sort ---
    {
        const int TOT   = L_LAY * D_DIM * KTOT;
        const int total = n * 32 + TOT + n4;
        embedprep_kernel<<<(total + 255) / 256, 256>>>(node_type, emb, xA, W, root, n, n4);
    }
    hist_kernel<<<(E + 255) / 256, 256>>>(edge_index, edge_type, E);
    {
        const int nb = (n4 + 1023) / 1024;
        scanA_kernel<<<nb, 1024>>>(n4);
        scanC_kernel<<<(n4 + 1 + 1023) / 1024, 1024>>>(n4, E);
    }
    reorder_kernel<<<(E + 255) / 256, 256>>>(edge_index, edge_type, E);

    const int agg_blocks  = (n4 * 32 + 255) / 256;
    const int gemm_blocks = (n + 127) / 128;

    for (int l = 0; l < L_LAY; l++) {
        const __half* xin = (l == 1) ? xB : xA;
        __half*       xout = (l == 0) ? xB : xA;

        agg_kernel<<<agg_blocks, 256>>>(xin, h, n4);

        if (l < L_LAY - 1) {
            gemm_mma_kernel<<<gemm_blocks, 256, SM_TOTAL>>>(
                xin, h,
                wt + (size_t)l * D_DIM * KTOT,
                bias + (size_t)l * D_DIM,
                xout, (float*)nullptr, n);
        } else {
            gemm_mma_kernel<<<gemm_blocks, 256, SM_TOTAL>>>(
                xin, h,
                wt + (size_t)l * D_DIM * KTOT,
                bias + (size_t)l * D_DIM,
                (__half*)nullptr, out, n);
        }
    }
}

// round 16
// speedup vs baseline: 1.2416x; 1.2416x over previous
#include <cuda_runtime.h>
#include <cuda_fp16.h>
#include <cstdint>

#define N_NODES 50000
#define E_MAX   600000
#define D_DIM   128
#define R_REL   4
#define L_LAY   3
#define KTOT    640           // 128 (root) + 4*128 (W)
#define KC      64            // K per pipeline stage
#define NCHUNK  (KTOT / KC)   // 10
#define NR4     (N_NODES * R_REL)

// ---------------------------------------------------------------------------
// Static device scratch (no runtime allocation allowed)
// ---------------------------------------------------------------------------
__device__ __half g_xA[(size_t)N_NODES * D_DIM];
__device__ __half g_xB[(size_t)N_NODES * D_DIM];
__device__ __half g_h [(size_t)N_NODES * R_REL * D_DIM];
// Transposed fp16 stacked weights: Wt[l][n][k], k in [0,640)
__device__ __half g_Wt[L_LAY][D_DIM][KTOT];
// Edge sort (key = dst*4 + relation)
__device__ int g_sorted[E_MAX];
__device__ __align__(16) int g_rowstart[NR4 + 4];
__device__ int g_cursor[NR4];
__device__ int g_bsum[256];

// ---------------------------------------------------------------------------
// Helpers
// ---------------------------------------------------------------------------
#define SWZ128(off) ((off) ^ (((off) >> 3) & 0x70))

__device__ __forceinline__ uint32_t smem_u32(const void* p) {
    uint32_t a;
    asm("{ .reg .u64 t; cvta.to.shared.u64 t, %1; cvt.u32.u64 %0, t; }"
        : "=r"(a) : "l"(p));
    return a;
}
__device__ __forceinline__ void cp16(uint32_t d, const void* s) {
    asm volatile("cp.async.cg.shared.global [%0], [%1], 16;" :: "r"(d), "l"(s));
}
__device__ __forceinline__ void cp16z(uint32_t d, const void* s, int bytes) {
    asm volatile("cp.async.cg.shared.global [%0], [%1], 16, %2;"
                 :: "r"(d), "l"(s), "r"(bytes));
}
#define CP_COMMIT() asm volatile("cp.async.commit_group;" ::: "memory")
#define CP_WAIT(N)  asm volatile("cp.async.wait_group %0;" :: "n"(N) : "memory")

__device__ __forceinline__ void ldmatrix_x4(uint32_t& r0, uint32_t& r1,
                                            uint32_t& r2, uint32_t& r3,
                                            uint32_t addr) {
    asm volatile("ldmatrix.sync.aligned.m8n8.x4.shared.b16 {%0,%1,%2,%3}, [%4];"
                 : "=r"(r0), "=r"(r1), "=r"(r2), "=r"(r3) : "r"(addr));
}
__device__ __forceinline__ void mma_f16(float* c, const uint32_t* a,
                                        uint32_t b0, uint32_t b1) {
    asm volatile(
        "mma.sync.aligned.m16n8k16.row.col.f32.f16.f16.f32 "
        "{%0,%1,%2,%3}, {%4,%5,%6,%7}, {%8,%9}, {%0,%1,%2,%3};"
        : "+f"(c[0]), "+f"(c[1]), "+f"(c[2]), "+f"(c[3])
        : "r"(a[0]), "r"(a[1]), "r"(a[2]), "r"(a[3]), "r"(b0), "r"(b1));
}

__device__ __forceinline__ uint32_t pack2h(float a, float b) {
    __half2 h = __floats2half2_rn(a, b);
    return *reinterpret_cast<uint32_t*>(&h);
}

// ---------------------------------------------------------------------------
// Kernel: embed -> fp16, weight prep, AND cursor zeroing (disjoint ranges)
// ---------------------------------------------------------------------------
__global__ void embedprep_kernel(const int* __restrict__ node_type,
                                 const float* __restrict__ emb,
                                 __half* __restrict__ x,
                                 const float* __restrict__ W,
                                 const float* __restrict__ root,
                                 int n, int n4)
{
    const int nEmb = n * 32;
    const int TOT  = L_LAY * D_DIM * KTOT;
    int idx = blockIdx.x * blockDim.x + threadIdx.x;
    if (idx < nEmb) {
        int node = idx >> 5;
        int q    = idx & 31;
        float4 v = reinterpret_cast<const float4*>(emb + (size_t)node_type[node] * D_DIM)[q];
        *reinterpret_cast<uint2*>(x + (size_t)node * D_DIM + q * 4) =
            make_uint2(pack2h(v.x, v.y), pack2h(v.z, v.w));
        return;
    }
    idx -= nEmb;
    if (idx < TOT) {
        int l  = idx / (D_DIM * KTOT);
        int r0 = idx % (D_DIM * KTOT);
        int nn = r0 / KTOT;
        int k  = r0 % KTOT;
        float v;
        if (k < D_DIM) {
            v = root[((size_t)l * D_DIM + k) * D_DIM + nn];
        } else {
            int kk = k - D_DIM;
            int r  = kk >> 7;
            int k2 = kk & 127;
            v = W[((((size_t)l * R_REL) + r) * D_DIM + k2) * D_DIM + nn];
        }
        g_Wt[l][nn][k] = __float2half_rn(v);
        return;
    }
    idx -= TOT;
    if (idx < n4) g_cursor[idx] = 0;
}

// ---------------------------------------------------------------------------
// Counting sort of edges by key = dst*4 + rel
// ---------------------------------------------------------------------------
__global__ void hist_kernel(const int* __restrict__ edge_index,
                            const int* __restrict__ edge_type, int E)
{
    int idx = blockIdx.x * blockDim.x + threadIdx.x;
    if (idx >= E) return;
    atomicAdd(&g_cursor[edge_index[E + idx] * 4 + edge_type[idx]], 1);
}

__global__ __launch_bounds__(1024)
void scanA_kernel(int n4)
{
    __shared__ int warp_sums[32];
    const int tid  = threadIdx.x;
    const int lane = tid & 31;
    const int wrp  = tid >> 5;
    const int i    = blockIdx.x * 1024 + tid;
    int v = (i < n4) ? g_cursor[i] : 0;
    int x = v;
    #pragma unroll
    for (int d = 1; d < 32; d <<= 1) {
        int t = __shfl_up_sync(0xffffffffu, x, d);
        if (lane >= d) x += t;
    }
    if (lane == 31) warp_sums[wrp] = x;
    __syncthreads();
    if (wrp == 0) {
        int s = warp_sums[lane];
        #pragma unroll
        for (int d = 1; d < 32; d <<= 1) {
            int t = __shfl_up_sync(0xffffffffu, s, d);
            if (lane >= d) s += t;
        }
        warp_sums[lane] = s;
    }
    __syncthreads();
    int excl = x - v + (wrp ? warp_sums[wrp - 1] : 0);
    if (i < n4) g_rowstart[i] = excl;
    if (tid == 1023) g_bsum[blockIdx.x] = excl + v;   // raw block total
}

__global__ __launch_bounds__(1024)
void scanC_kernel(int n4, int E)
{
    __shared__ int s_off;
    const int tid = threadIdx.x;
    if (tid == 0) s_off = 0;
    __syncthreads();
    int p = 0;
    for (int i = tid; i < blockIdx.x; i += blockDim.x) p += g_bsum[i];
    if (p) atomicAdd(&s_off, p);
    __syncthreads();
    const int off = s_off;
    const int i = blockIdx.x * 1024 + tid;
    if (i < n4) {
        int v = g_rowstart[i] + off;
        g_rowstart[i] = v;
        g_cursor[i]   = v;
    } else if (i == n4) {
        g_rowstart[n4] = E;
    }
}

__global__ void reorder_kernel(const int* __restrict__ edge_index,
                               const int* __restrict__ edge_type, int E)
{
    int idx = blockIdx.x * blockDim.x + threadIdx.x;
    if (idx >= E) return;
    int key = edge_index[E + idx] * 4 + edge_type[idx];
    int pos = atomicAdd(&g_cursor[key], 1);
    g_sorted[pos] = edge_index[idx];   // src only
}

// ---------------------------------------------------------------------------
// Kernel: CSR aggregation (R14 shape). One warp per dst node; four
// compile-time relation-segment loops; fixed-register accumulators.
// CSR boundaries hoisted: one int4 + one scalar load upfront.
// ---------------------------------------------------------------------------
__global__ __launch_bounds__(256)
void agg_kernel(const __half* __restrict__ x,
                __half* __restrict__ h, int n)
{
    int w = (blockIdx.x * blockDim.x + threadIdx.x) >> 5;
    int lane = threadIdx.x & 31;
    if (w >= n) return;

    int4 b4 = *reinterpret_cast<const int4*>(&g_rowstart[w * 4]);
    int b[5];
    b[0] = b4.x; b[1] = b4.y; b[2] = b4.z; b[3] = b4.w;
    b[4] = g_rowstart[w * 4 + 4];

    #pragma unroll
    for (int r = 0; r < R_REL; r++) {
        const int e0 = b[r];
        const int e1 = b[r + 1];
        float a0 = 0.f, a1 = 0.f, a2 = 0.f, a3 = 0.f;
        #pragma unroll 4
        for (int e = e0; e < e1; e++) {
            int src = __ldg(&g_sorted[e]);
            uint2 v = *reinterpret_cast<const uint2*>(
                x + (size_t)src * D_DIM + lane * 4);
            float2 f0 = __half22float2(*reinterpret_cast<__half2*>(&v.x));
            float2 f1 = __half22float2(*reinterpret_cast<__half2*>(&v.y));
            a0 += f0.x; a1 += f0.y; a2 += f1.x; a3 += f1.y;
        }
        size_t o = (size_t)w * (R_REL * D_DIM) + r * D_DIM + lane * 4;
        *reinterpret_cast<uint2*>(h + o) =
            make_uint2(pack2h(a0, a1), pack2h(a2, a3));
    }
}

// ---------------------------------------------------------------------------
// GEMM: y[m,0:128] = lrelu( [x|h][m,0:640] @ Wt^T + bias )   (unchanged)
// ---------------------------------------------------------------------------
#define ST_A   0
#define ST_B   16384
#define ST_SIZE 32768
#define SM_TOTAL (2 * ST_SIZE)

__global__ __launch_bounds__(256, 2)
void gemm_mma_kernel(const __half* __restrict__ x,
                     const __half* __restrict__ h,
                     const __half* __restrict__ Wt,    // [128][640]
                     const float* __restrict__ bias_l,
                     __half* __restrict__ yh,          // null on final
                     float* __restrict__ yf32,         // null unless final
                     int n)
{
    extern __shared__ __align__(1024) char smem[];
    const uint32_t sb = smem_u32(smem);
    const int tid    = threadIdx.x;
    const int lane   = tid & 31;
    const int wid    = tid >> 5;
    const int warp_m = wid >> 2;
    const int warp_n = wid & 3;
    const int m0     = blockIdx.x * 128;

    float acc[4][4][4];
    #pragma unroll
    for (int i = 0; i < 4; i++)
        #pragma unroll
        for (int j = 0; j < 4; j++)
            #pragma unroll
            for (int q = 0; q < 4; q++) acc[i][j][q] = 0.f;

    auto load_stage = [&](int stage, int c) {
        const __half* A;
        int lda;
        if (c < 2) { A = x + c * KC; lda = D_DIM; }
        else       { A = h + (c - 2) * KC; lda = R_REL * D_DIM; }
        const uint32_t base = sb + stage * ST_SIZE;
        #pragma unroll
        for (int it = 0; it < 4; it++) {
            int f   = it * 256 + tid;
            int row = f >> 3;
            int q   = f & 7;
            uint32_t off = SWZ128((uint32_t)(row * 128 + q * 16));
            int bytes = (m0 + row < n) ? 16 : 0;
            cp16z(base + ST_A + off, A + (size_t)(m0 + row) * lda + q * 8, bytes);
        }
        #pragma unroll
        for (int it = 0; it < 4; it++) {
            int f   = it * 256 + tid;
            int row = f >> 3;
            int q   = f & 7;
            uint32_t off = SWZ128((uint32_t)(row * 128 + q * 16));
            cp16(base + ST_B + off, Wt + (size_t)row * KTOT + c * KC + q * 8);
        }
    };

    load_stage(0, 0);
    CP_COMMIT();

    for (int c = 0; c < NCHUNK; c++) {
        if (c + 1 < NCHUNK) {
            load_stage((c + 1) & 1, c + 1);
            CP_COMMIT();
            CP_WAIT(1);
        } else {
            CP_WAIT(0);
        }
        __syncthreads();

        const uint32_t base = sb + (c & 1) * ST_SIZE;
        #pragma unroll
        for (int ks = 0; ks < 4; ks++) {
            const int k0 = ks * 16;
            uint32_t b[2][4];
            #pragma unroll
            for (int p = 0; p < 2; p++) {
                int nb   = warp_n * 32 + p * 16;
                int row  = nb + (lane & 7) + ((lane >> 4) << 3);
                uint32_t off = SWZ128((uint32_t)(row * 128 + k0 * 2 + ((lane & 8) ? 16 : 0)));
                ldmatrix_x4(b[p][0], b[p][1], b[p][2], b[p][3], base + ST_B + off);
            }
            #pragma unroll
            for (int m = 0; m < 4; m++) {
                int row  = warp_m * 64 + m * 16 + (lane & 15);
                uint32_t off = SWZ128((uint32_t)(row * 128 + k0 * 2 + ((lane >> 4) << 4)));
                uint32_t a[4];
                ldmatrix_x4(a[0], a[1], a[2], a[3], base + ST_A + off);
                #pragma unroll
                for (int p = 0; p < 2; p++) {
                    #pragma unroll
                    for (int t = 0; t < 2; t++) {
                        int nt = p * 2 + t;
                        mma_f16(acc[m][nt], a, b[p][t * 2], b[p][t * 2 + 1]);
                    }
                }
            }
        }
        __syncthreads();
    }

    // ---- epilogue: bias + leaky_relu ----
    #pragma unroll
    for (int nt = 0; nt < 4; nt++) {
        int col = warp_n * 32 + nt * 8 + (lane & 3) * 2;
        float2 b = *reinterpret_cast<const float2*>(bias_l + col);
        #pragma unroll
        for (int m = 0; m < 4; m++) {
            int row0 = m0 + warp_m * 64 + m * 16 + (lane >> 2);
            #pragma unroll
            for (int half = 0; half < 2; half++) {
                int row = row0 + half * 8;
                if (row < n) {
                    float v0 = acc[m][nt][half * 2 + 0] + b.x;
                    float v1 = acc[m][nt][half * 2 + 1] + b.y;
                    v0 = v0 > 0.f ? v0 : 0.01f * v0;
                    v1 = v1 > 0.f ? v1 : 0.01f * v1;
                    if (yf32) {
                        *reinterpret_cast<float2*>(yf32 + (size_t)row * D_DIM + col) =
                            make_float2(v0, v1);
                    } else {
                        *reinterpret_cast<uint32_t*>(yh + (size_t)row * D_DIM + col) =
                            pack2h(v0, v1);
                    }
                }
            }
        }
    }
}

// ---------------------------------------------------------------------------
// Launch
// ---------------------------------------------------------------------------
extern "C" void kernel_launch(void* const* d_in, const int* in_sizes, int n_in,
                              void* d_out, int out_size)
{
    const int*   node_type  = (const int*)  d_in[0];
    const int*   edge_index = (const int*)  d_in[1];
    const int*   edge_type  = (const int*)  d_in[2];
    const float* emb        = (const float*)d_in[3];
    const float* W          = (const float*)d_in[4];   // [L,R,D,D]
    const float* root       = (const float*)d_in[5];   // [L,D,D]
    const float* bias       = (const float*)d_in[6];   // [L,D]
    float*       out        = (float*)d_out;

    const int n  = in_sizes[0];
    const int E  = in_sizes[2];
    const int n4 = n * R_REL;

    __half *xA, *xB, *h, *wt;
    cudaGetSymbolAddress((void**)&xA,  g_xA);
    cudaGetSymbolAddress((void**)&xB,  g_xB);
    cudaGetSymbolAddress((void**)&h,   g_h);
    cudaGetSymbolAddress((void**)&wt,  g_Wt);

    cudaFuncSetAttribute(gemm_mma_kernel,
                         cudaFuncAttributeMaxDynamicSharedMemorySize, SM_TOTAL);

    // --- one-time per launch: embed+prep+cursor-zero, edge sort ---
    {
        const int TOT   = L_LAY * D_DIM * KTOT;
        const int total = n * 32 + TOT + n4;
        embedprep_kernel<<<(total + 255) / 256, 256>>>(node_type, emb, xA, W, root, n, n4);
    }
    hist_kernel<<<(E + 255) / 256, 256>>>(edge_index, edge_type, E);
    {
        const int nb = (n4 + 1023) / 1024;
        scanA_kernel<<<nb, 1024>>>(n4);
        scanC_kernel<<<(n4 + 1 + 1023) / 1024, 1024>>>(n4, E);
    }
    reorder_kernel<<<(E + 255) / 256, 256>>>(edge_index, edge_type, E);

    const int agg_blocks  = (n * 32 + 255) / 256;
    const int gemm_blocks = (n + 127) / 128;

    for (int l = 0; l < L_LAY; l++) {
        const __half* xin = (l == 1) ? xB : xA;
        __half*       xout = (l == 0) ? xB : xA;

        agg_kernel<<<agg_blocks, 256>>>(xin, h, n);

        if (l < L_LAY - 1) {
            gemm_mma_kernel<<<gemm_blocks, 256, SM_TOTAL>>>(
                xin, h,
                wt + (size_t)l * D_DIM * KTOT,
                bias + (size_t)l * D_DIM,
                xout, (float*)nullptr, n);
        } else {
            gemm_mma_kernel<<<gemm_blocks, 256, SM_TOTAL>>>(
                xin, h,
                wt + (size_t)l * D_DIM * KTOT,
                bias + (size_t)l * D_DIM,
                (__half*)nullptr, out, n);
        }
    }
}